// round 16
// baseline (speedup 1.0000x reference)
#include <cuda_runtime.h>
#include <cstdint>

// ============================================================================
// MoeMatmul: out[2048,14336] = state[2048,4096] @ w[e][14336,4096]^T  (fp32)
// SINGLE LAUNCH: mma.sync m16n8k8 tf32 GEMM reading state/w directly; both
// operands consumed raw (HW truncation to tf32; calibrated bias model:
// 2x half-ulp ~= 7.3e-4 deterministic rel_err, < 1e-3 threshold).
// ldmatrix b16 fragments, cp.async 3-stage pipeline, tile 128x128,
// 256 threads, warp tile 32x64, 2 CTAs/SM.  (R4/R14 GEMM, unchanged.)
// ============================================================================

#define M_TOTAL 2048
#define K_TOTAL 4096
#define N_TOTAL 14336

#define BM 128
#define BN 128
#define BK 32
#define STAGES 3
#define NK (K_TOTAL / BK)          // 128
#define NTILES ((M_TOTAL / BM) * (N_TOTAL / BN))   // 1792
#define LDS_A 36                   // padded row stride (floats): 144B
#define THREADS 256

#define A_STAGE_FLOATS (BM * LDS_A)              // 4608
#define B_STAGE_FLOATS (BN * LDS_A)              // 4608
#define A_STAGE_BYTES (A_STAGE_FLOATS * 4)
#define B_STAGE_BYTES (B_STAGE_FLOATS * 4)
#define SMEM_BYTES ((STAGES * (A_STAGE_FLOATS + B_STAGE_FLOATS)) * 4)  // 110592

// ---------------------------------------------------------------------------
// PTX helpers (base-target features only)
// ---------------------------------------------------------------------------
__device__ __forceinline__ uint32_t smem_u32(const void* p) {
    uint32_t a;
    asm("{ .reg .u64 t; cvta.to.shared.u64 t, %1; cvt.u32.u64 %0, t; }" : "=r"(a) : "l"(p));
    return a;
}

__device__ __forceinline__ void cp_async16(uint32_t saddr, const void* g) {
    asm volatile("cp.async.cg.shared.global [%0], [%1], 16;" :: "r"(saddr), "l"(g));
}

__device__ __forceinline__ void cp_commit() {
    asm volatile("cp.async.commit_group;" ::: "memory");
}

template <int N>
__device__ __forceinline__ void cp_wait() {
    asm volatile("cp.async.wait_group %0;" :: "n"(N) : "memory");
}

__device__ __forceinline__ void ldsm_x4(uint32_t& r0, uint32_t& r1, uint32_t& r2, uint32_t& r3,
                                        uint32_t addr) {
    asm volatile("ldmatrix.sync.aligned.m8n8.x4.shared.b16 {%0,%1,%2,%3}, [%4];"
                 : "=r"(r0), "=r"(r1), "=r"(r2), "=r"(r3) : "r"(addr));
}

__device__ __forceinline__ void mma_tf32(float* c, const uint32_t* a, const uint32_t* b) {
    asm volatile(
        "mma.sync.aligned.m16n8k8.row.col.f32.tf32.tf32.f32 "
        "{%0,%1,%2,%3}, {%4,%5,%6,%7}, {%8,%9}, {%0,%1,%2,%3};"
        : "+f"(c[0]), "+f"(c[1]), "+f"(c[2]), "+f"(c[3])
        : "r"(a[0]), "r"(a[1]), "r"(a[2]), "r"(a[3]), "r"(b[0]), "r"(b[1]));
}

// ---------------------------------------------------------------------------
// GEMM (tile 128x128, warp tile 32x64) — both operands HW-truncated to tf32
// ---------------------------------------------------------------------------
__global__ void __launch_bounds__(THREADS, 2) moe_mma_kernel(
    const float* __restrict__ A,
    const int*   __restrict__ expert_id,
    const float* __restrict__ W,
    float*       __restrict__ out)
{
    extern __shared__ float smem[];
    const int tid  = threadIdx.x;
    const int lane = tid & 31;
    const int wid  = tid >> 5;
    const int wm   = wid & 3;          // 4 warps along M (32 rows each)
    const int wn   = wid >> 2;         // 2 warps along N (64 cols each)

    // m fastest: 16 M-CTAs of one N-panel co-resident -> W panel reused from L2
    const int bx = blockIdx.x;
    const int m0 = (bx & 15) * BM;
    const int n0 = (bx >> 4) * BN;

    const long long e = expert_id[0];
    const float* __restrict__ Wb = W + e * (long long)N_TOTAL * (long long)K_TOTAL;

    float* sa = smem;                                   // [STAGES][BM][LDS_A]
    float* sb = smem + STAGES * A_STAGE_FLOATS;         // [STAGES][BN][LDS_A]
    const uint32_t sa_u = smem_u32(sa);
    const uint32_t sb_u = smem_u32(sb);

    // cp.async chunk mapping: row = tid>>3, kc16 = tid&7
    const int c0r = tid >> 3, c0k = tid & 7;

    auto load_stage = [&](int s, int kt) {
        const int k0 = kt * BK;
        #pragma unroll
        for (int i = 0; i < 4; i++) {
            const int row = c0r + i * 32;
            const uint32_t so = (uint32_t)(row * LDS_A + c0k * 4) * 4u;
            cp_async16(sa_u + (uint32_t)(s * A_STAGE_BYTES) + so,
                       A + (size_t)(m0 + row) * K_TOTAL + k0 + c0k * 4);
            cp_async16(sb_u + (uint32_t)(s * B_STAGE_BYTES) + so,
                       Wb + (size_t)(n0 + row) * K_TOTAL + k0 + c0k * 4);
        }
        cp_commit();
    };

    load_stage(0, 0);
    load_stage(1, 1);

    float acc[2][8][4];
    #pragma unroll
    for (int mt = 0; mt < 2; mt++)
        #pragma unroll
        for (int nt = 0; nt < 8; nt++)
            #pragma unroll
            for (int q = 0; q < 4; q++) acc[mt][nt][q] = 0.0f;

    // ldmatrix per-thread source addresses (b16 8x8 tiles over fp32 data)
    const int a_r  = (lane & 7) + ((lane >> 3) & 1) * 8;
    const int a_c4 = (lane >> 4) * 4;
    const uint32_t a_base = sa_u + (uint32_t)(((wm * 32 + a_r) * LDS_A + a_c4) * 4);
    const int b_r  = (lane & 7) + ((lane >> 4) & 1) * 8;
    const int b_c4 = ((lane >> 3) & 1) * 4;
    const uint32_t b_base = sb_u + (uint32_t)(((wn * 64 + b_r) * LDS_A + b_c4) * 4);

    const int fr = lane >> 2;
    const int fc = lane & 3;

    int s = 0;
    #pragma unroll 1
    for (int i = 0; i < NK; i++) {
        cp_wait<STAGES - 2>();
        __syncthreads();

        if (i + STAGES - 1 < NK) {
            int sl = s + (STAGES - 1);
            if (sl >= STAGES) sl -= STAGES;
            load_stage(sl, i + STAGES - 1);
        }

        const uint32_t a_st = a_base + (uint32_t)(s * A_STAGE_BYTES);
        const uint32_t b_st = b_base + (uint32_t)(s * B_STAGE_BYTES);

        #pragma unroll
        for (int kt = 0; kt < 4; kt++) {
            const uint32_t kbb = (uint32_t)(kt * 8 * 4);
            uint32_t af[2][4], bf[8][2];
            #pragma unroll
            for (int mt = 0; mt < 2; mt++)
                ldsm_x4(af[mt][0], af[mt][1], af[mt][2], af[mt][3],
                        a_st + (uint32_t)(mt * 16 * LDS_A * 4) + kbb);
            #pragma unroll
            for (int p = 0; p < 4; p++)
                ldsm_x4(bf[2 * p][0], bf[2 * p][1], bf[2 * p + 1][0], bf[2 * p + 1][1],
                        b_st + (uint32_t)(p * 16 * LDS_A * 4) + kbb);
            #pragma unroll
            for (int mt = 0; mt < 2; mt++)
                #pragma unroll
                for (int nt = 0; nt < 8; nt++)
                    mma_tf32(acc[mt][nt], af[mt], bf[nt]);
        }

        if (++s == STAGES) s = 0;
    }

    // ---- epilogue ----
    const int orow = m0 + wm * 32 + fr;
    const int ocol = n0 + wn * 64 + 2 * fc;
    #pragma unroll
    for (int mt = 0; mt < 2; mt++) {
        float* r0 = out + (size_t)(orow + mt * 16) * N_TOTAL + ocol;
        float* r1 = out + (size_t)(orow + mt * 16 + 8) * N_TOTAL + ocol;
        #pragma unroll
        for (int nt = 0; nt < 8; nt++) {
            *reinterpret_cast<float2*>(r0 + nt * 8) = make_float2(acc[mt][nt][0], acc[mt][nt][1]);
            *reinterpret_cast<float2*>(r1 + nt * 8) = make_float2(acc[mt][nt][2], acc[mt][nt][3]);
        }
    }
}

// ---------------------------------------------------------------------------
// Host launch
// ---------------------------------------------------------------------------
extern "C" void kernel_launch(void* const* d_in, const int* in_sizes, int n_in,
                              void* d_out, int out_size) {
    const float* state = (const float*)d_in[0];
    const int*   eid   = (const int*)d_in[1];
    const float* w     = (const float*)d_in[2];
    float* out = (float*)d_out;

    static bool configured = false;
    if (!configured) {
        cudaFuncSetAttribute(moe_mma_kernel,
                             cudaFuncAttributeMaxDynamicSharedMemorySize, SMEM_BYTES);
        configured = true;
    }

    moe_mma_kernel<<<NTILES, THREADS, SMEM_BYTES>>>(state, eid, w, out);
}

// round 17
// speedup vs baseline: 1.0002x; 1.0002x over previous
#include <cuda_runtime.h>
#include <cstdint>

// ============================================================================
// MoeMatmul: out[2048,14336] = state[2048,4096] @ w[e][14336,4096]^T  (fp32)
// SINGLE LAUNCH: mma.sync m16n8k8 tf32 GEMM reading state/w directly; both
// operands consumed raw (HW truncation to tf32; calibrated bias model:
// 2x half-ulp ~= 7.3e-4 deterministic rel_err, < 1e-3 threshold).
// ldmatrix b16 fragments, cp.async 3-stage pipeline, tile 128x128,
// 256 threads, warp tile 32x64, 2 CTAs/SM.  (R4/R14 GEMM, unchanged.)
// ============================================================================

#define M_TOTAL 2048
#define K_TOTAL 4096
#define N_TOTAL 14336

#define BM 128
#define BN 128
#define BK 32
#define STAGES 3
#define NK (K_TOTAL / BK)          // 128
#define NTILES ((M_TOTAL / BM) * (N_TOTAL / BN))   // 1792
#define LDS_A 36                   // padded row stride (floats): 144B
#define THREADS 256

#define A_STAGE_FLOATS (BM * LDS_A)              // 4608
#define B_STAGE_FLOATS (BN * LDS_A)              // 4608
#define A_STAGE_BYTES (A_STAGE_FLOATS * 4)
#define B_STAGE_BYTES (B_STAGE_FLOATS * 4)
#define SMEM_BYTES ((STAGES * (A_STAGE_FLOATS + B_STAGE_FLOATS)) * 4)  // 110592

// ---------------------------------------------------------------------------
// PTX helpers (base-target features only)
// ---------------------------------------------------------------------------
__device__ __forceinline__ uint32_t smem_u32(const void* p) {
    uint32_t a;
    asm("{ .reg .u64 t; cvta.to.shared.u64 t, %1; cvt.u32.u64 %0, t; }" : "=r"(a) : "l"(p));
    return a;
}

__device__ __forceinline__ void cp_async16(uint32_t saddr, const void* g) {
    asm volatile("cp.async.cg.shared.global [%0], [%1], 16;" :: "r"(saddr), "l"(g));
}

__device__ __forceinline__ void cp_commit() {
    asm volatile("cp.async.commit_group;" ::: "memory");
}

template <int N>
__device__ __forceinline__ void cp_wait() {
    asm volatile("cp.async.wait_group %0;" :: "n"(N) : "memory");
}

__device__ __forceinline__ void ldsm_x4(uint32_t& r0, uint32_t& r1, uint32_t& r2, uint32_t& r3,
                                        uint32_t addr) {
    asm volatile("ldmatrix.sync.aligned.m8n8.x4.shared.b16 {%0,%1,%2,%3}, [%4];"
                 : "=r"(r0), "=r"(r1), "=r"(r2), "=r"(r3) : "r"(addr));
}

__device__ __forceinline__ void mma_tf32(float* c, const uint32_t* a, const uint32_t* b) {
    asm volatile(
        "mma.sync.aligned.m16n8k8.row.col.f32.tf32.tf32.f32 "
        "{%0,%1,%2,%3}, {%4,%5,%6,%7}, {%8,%9}, {%0,%1,%2,%3};"
        : "+f"(c[0]), "+f"(c[1]), "+f"(c[2]), "+f"(c[3])
        : "r"(a[0]), "r"(a[1]), "r"(a[2]), "r"(a[3]), "r"(b[0]), "r"(b[1]));
}

// ---------------------------------------------------------------------------
// GEMM (tile 128x128, warp tile 32x64) — both operands HW-truncated to tf32
// ---------------------------------------------------------------------------
__global__ void __launch_bounds__(THREADS, 2) moe_mma_kernel(
    const float* __restrict__ A,
    const int*   __restrict__ expert_id,
    const float* __restrict__ W,
    float*       __restrict__ out)
{
    extern __shared__ float smem[];
    const int tid  = threadIdx.x;
    const int lane = tid & 31;
    const int wid  = tid >> 5;
    const int wm   = wid & 3;          // 4 warps along M (32 rows each)
    const int wn   = wid >> 2;         // 2 warps along N (64 cols each)

    // m fastest: 16 M-CTAs of one N-panel co-resident -> W panel reused from L2
    const int bx = blockIdx.x;
    const int m0 = (bx & 15) * BM;
    const int n0 = (bx >> 4) * BN;

    const long long e = expert_id[0];
    const float* __restrict__ Wb = W + e * (long long)N_TOTAL * (long long)K_TOTAL;

    float* sa = smem;                                   // [STAGES][BM][LDS_A]
    float* sb = smem + STAGES * A_STAGE_FLOATS;         // [STAGES][BN][LDS_A]
    const uint32_t sa_u = smem_u32(sa);
    const uint32_t sb_u = smem_u32(sb);

    // cp.async chunk mapping: row = tid>>3, kc16 = tid&7
    const int c0r = tid >> 3, c0k = tid & 7;

    auto load_stage = [&](int s, int kt) {
        const int k0 = kt * BK;
        #pragma unroll
        for (int i = 0; i < 4; i++) {
            const int row = c0r + i * 32;
            const uint32_t so = (uint32_t)(row * LDS_A + c0k * 4) * 4u;
            cp_async16(sa_u + (uint32_t)(s * A_STAGE_BYTES) + so,
                       A + (size_t)(m0 + row) * K_TOTAL + k0 + c0k * 4);
            cp_async16(sb_u + (uint32_t)(s * B_STAGE_BYTES) + so,
                       Wb + (size_t)(n0 + row) * K_TOTAL + k0 + c0k * 4);
        }
        cp_commit();
    };

    load_stage(0, 0);
    load_stage(1, 1);

    float acc[2][8][4];
    #pragma unroll
    for (int mt = 0; mt < 2; mt++)
        #pragma unroll
        for (int nt = 0; nt < 8; nt++)
            #pragma unroll
            for (int q = 0; q < 4; q++) acc[mt][nt][q] = 0.0f;

    // ldmatrix per-thread source addresses (b16 8x8 tiles over fp32 data)
    const int a_r  = (lane & 7) + ((lane >> 3) & 1) * 8;
    const int a_c4 = (lane >> 4) * 4;
    const uint32_t a_base = sa_u + (uint32_t)(((wm * 32 + a_r) * LDS_A + a_c4) * 4);
    const int b_r  = (lane & 7) + ((lane >> 4) & 1) * 8;
    const int b_c4 = ((lane >> 3) & 1) * 4;
    const uint32_t b_base = sb_u + (uint32_t)(((wn * 64 + b_r) * LDS_A + b_c4) * 4);

    const int fr = lane >> 2;
    const int fc = lane & 3;

    int s = 0;
    #pragma unroll 1
    for (int i = 0; i < NK; i++) {
        cp_wait<STAGES - 2>();
        __syncthreads();

        if (i + STAGES - 1 < NK) {
            int sl = s + (STAGES - 1);
            if (sl >= STAGES) sl -= STAGES;
            load_stage(sl, i + STAGES - 1);
        }

        const uint32_t a_st = a_base + (uint32_t)(s * A_STAGE_BYTES);
        const uint32_t b_st = b_base + (uint32_t)(s * B_STAGE_BYTES);

        #pragma unroll
        for (int kt = 0; kt < 4; kt++) {
            const uint32_t kbb = (uint32_t)(kt * 8 * 4);
            uint32_t af[2][4], bf[8][2];
            #pragma unroll
            for (int mt = 0; mt < 2; mt++)
                ldsm_x4(af[mt][0], af[mt][1], af[mt][2], af[mt][3],
                        a_st + (uint32_t)(mt * 16 * LDS_A * 4) + kbb);
            #pragma unroll
            for (int p = 0; p < 4; p++)
                ldsm_x4(bf[2 * p][0], bf[2 * p][1], bf[2 * p + 1][0], bf[2 * p + 1][1],
                        b_st + (uint32_t)(p * 16 * LDS_A * 4) + kbb);
            #pragma unroll
            for (int mt = 0; mt < 2; mt++)
                #pragma unroll
                for (int nt = 0; nt < 8; nt++)
                    mma_tf32(acc[mt][nt], af[mt], bf[nt]);
        }

        if (++s == STAGES) s = 0;
    }

    // ---- epilogue ----
    const int orow = m0 + wm * 32 + fr;
    const int ocol = n0 + wn * 64 + 2 * fc;
    #pragma unroll
    for (int mt = 0; mt < 2; mt++) {
        float* r0 = out + (size_t)(orow + mt * 16) * N_TOTAL + ocol;
        float* r1 = out + (size_t)(orow + mt * 16 + 8) * N_TOTAL + ocol;
        #pragma unroll
        for (int nt = 0; nt < 8; nt++) {
            *reinterpret_cast<float2*>(r0 + nt * 8) = make_float2(acc[mt][nt][0], acc[mt][nt][1]);
            *reinterpret_cast<float2*>(r1 + nt * 8) = make_float2(acc[mt][nt][2], acc[mt][nt][3]);
        }
    }
}

// ---------------------------------------------------------------------------
// Host launch
// ---------------------------------------------------------------------------
extern "C" void kernel_launch(void* const* d_in, const int* in_sizes, int n_in,
                              void* d_out, int out_size) {
    const float* state = (const float*)d_in[0];
    const int*   eid   = (const int*)d_in[1];
    const float* w     = (const float*)d_in[2];
    float* out = (float*)d_out;

    static bool configured = false;
    if (!configured) {
        cudaFuncSetAttribute(moe_mma_kernel,
                             cudaFuncAttributeMaxDynamicSharedMemorySize, SMEM_BYTES);
        configured = true;
    }

    moe_mma_kernel<<<NTILES, THREADS, SMEM_BYTES>>>(state, eid, w, out);
}